// round 12
// baseline (speedup 1.0000x reference)
#include <cuda_runtime.h>
#include <cstdint>

// Problem constants
#define BB 48
#define LL 128
#define DD 1024
#define HH 150      // ffnn out
#define HP 151      // +bias col
#define OO 9
#define LDX 160     // padded feature stride

#define N_CELLS (LL*LL)              // 16384
#define SCORE_ELEMS (BB*LL*LL*OO)    // 7077888
#define RESULT_ELEMS (BB*LL*LL)      // 786432
#define UCOLS (OO*LDX)               // 1440
#define PROJ_ROWS (BB*LL)            // 6144

#define FULLMASK 0xFFFFFFFFu

// ---------------- static device scratch --------------------------------------
__device__ float Xg[(size_t)PROJ_ROWS*LDX];           // [6144][160]
__device__ float Yg[(size_t)PROJ_ROWS*LDX];
__device__ float Pg[(size_t)4*PROJ_ROWS*LDX];         // split-K partials [side*2+half]
__device__ float Ug[(size_t)BB*LL*UCOLS];             // [6144][1440]
__device__ float Sg[(size_t)SCORE_ELEMS];             // [b][x][o][y]
__device__ float Wpad[(size_t)OO*LDX*LDX];            // [9][160][160]
__device__ unsigned KeyG[(size_t)BB*N_CELLS];         // sort keys (desc-orderable)
__device__ __align__(16) unsigned char AnsG[(size_t)BB*N_CELLS];  // argmax labels

// ---------------- f32x2 helpers ---------------------------------------------
__device__ __forceinline__ void fma2(unsigned long long& d, unsigned long long a,
                                     unsigned long long b) {
    asm("fma.rn.f32x2 %0, %1, %2, %0;" : "+l"(d) : "l"(a), "l"(b));
}
__device__ __forceinline__ unsigned long long pack2(float x) {
    unsigned long long r;
    asm("mov.b64 %0, {%1, %1};" : "=l"(r) : "f"(x));
    return r;
}
__device__ __forceinline__ float2 unpack2(unsigned long long v) {
    float2 f;
    asm("mov.b64 {%0, %1}, %2;" : "=f"(f.x), "=f"(f.y) : "l"(v));
    return f;
}

// 8-row x 8-col micro step
__device__ __forceinline__ void micro_step8(const float* __restrict__ aRow,
                                            const float* __restrict__ bRow,
                                            unsigned long long acc[8][4]) {
    float4 a0 = *(const float4*)(aRow);
    float4 a1 = *(const float4*)(aRow + 4);
    ulonglong2 q0 = *(const ulonglong2*)(bRow);
    ulonglong2 q1 = *(const ulonglong2*)(bRow + 4);
    unsigned long long bb[4] = {q0.x, q0.y, q1.x, q1.y};
    float av[8] = {a0.x, a0.y, a0.z, a0.w, a1.x, a1.y, a1.z, a1.w};
#pragma unroll
    for (int r = 0; r < 8; r++) {
        unsigned long long ap = pack2(av[r]);
#pragma unroll
        for (int p = 0; p < 4; p++) fma2(acc[r][p], ap, bb[p]);
    }
}

// 16-row x 8-col micro step
__device__ __forceinline__ void micro_step16(const float* __restrict__ aRow,
                                             const float* __restrict__ bRow,
                                             unsigned long long acc[16][4]) {
    float4 a0 = *(const float4*)(aRow);
    float4 a1 = *(const float4*)(aRow + 4);
    float4 a2 = *(const float4*)(aRow + 8);
    float4 a3 = *(const float4*)(aRow + 12);
    ulonglong2 q0 = *(const ulonglong2*)(bRow);
    ulonglong2 q1 = *(const ulonglong2*)(bRow + 4);
    unsigned long long bb[4] = {q0.x, q0.y, q1.x, q1.y};
    float av[16] = {a0.x, a0.y, a0.z, a0.w, a1.x, a1.y, a1.z, a1.w,
                    a2.x, a2.y, a2.z, a2.w, a3.x, a3.y, a3.z, a3.w};
#pragma unroll
    for (int r = 0; r < 16; r++) {
        unsigned long long ap = pack2(av[r]);
#pragma unroll
        for (int p = 0; p < 4; p++) fma2(acc[r][p], ap, bb[p]);
    }
}

// ============================================================================
// Kernel 0: pad W [9][151][151] -> Wpad [9][160][160] (zeros elsewhere)
// ============================================================================
__global__ __launch_bounds__(256) void pad_w_kernel(const float* __restrict__ Wb) {
    int idx = blockIdx.x * 256 + threadIdx.x;
    if (idx >= OO * LDX * LDX) return;
    int o = idx / (LDX * LDX);
    int r = idx % (LDX * LDX);
    int i = r / LDX, j = r % LDX;
    Wpad[idx] = (i < HP && j < HP) ? Wb[(size_t)o * HP * HP + i * HP + j] : 0.f;
}

// ============================================================================
// Kernel 1a: split-K projection partials.
// grid (96, 2, 2): x = 64-row tile, y = side (X/Y), z = K half (512 each).
// ============================================================================
__global__ __launch_bounds__(160, 3) void proj_partial(
    const float* __restrict__ bert,
    const float* __restrict__ wS, const float* __restrict__ wE) {
    const int z = blockIdx.y;
    const int h = blockIdx.z;
    const float* w = z ? wE : wS;
    float* outp = Pg + (size_t)(z * 2 + h) * PROJ_ROWS * LDX;
    const int mBase = blockIdx.x * 64;
    const int kBase = h * 512;

    __shared__ alignas(16) float As[16][72];
    __shared__ alignas(16) float Bs[16][168];

    const int t = threadIdx.x;
    const int tx = t % 20, ty = t / 20;

    const int aRow0 = t >> 2, aRow1 = (t + 160) >> 2;
    const bool aV1 = (t < 96);
    const int kq = t & 3;
    int bCol[4];
#pragma unroll
    for (int s = 0; s < 4; s++) bCol[s] = (t + 160 * s) >> 2;

    float4 aF[2], bF[4];
    const float4 z4 = make_float4(0.f, 0.f, 0.f, 0.f);
    auto loadT = [&](int k0) {
        aF[0] = *(const float4*)(bert + (size_t)(mBase + aRow0) * DD + k0 + kq * 4);
        aF[1] = aV1 ? *(const float4*)(bert + (size_t)(mBase + aRow1) * DD + k0 + kq * 4) : z4;
#pragma unroll
        for (int s = 0; s < 4; s++)
            bF[s] = (bCol[s] < HH)
                  ? *(const float4*)(w + (size_t)bCol[s] * DD + k0 + kq * 4) : z4;
    };

    unsigned long long acc[8][4];
#pragma unroll
    for (int r = 0; r < 8; r++)
#pragma unroll
        for (int p = 0; p < 4; p++) acc[r][p] = 0ull;

    loadT(kBase);
    for (int k0 = kBase; k0 < kBase + 512; k0 += 16) {
        {
            const float* f = (const float*)&aF[0];
#pragma unroll
            for (int c = 0; c < 4; c++) As[kq * 4 + c][aRow0] = f[c];
        }
        if (aV1) {
            const float* f = (const float*)&aF[1];
#pragma unroll
            for (int c = 0; c < 4; c++) As[kq * 4 + c][aRow1] = f[c];
        }
#pragma unroll
        for (int s = 0; s < 4; s++) {
            const float* f = (const float*)&bF[s];
#pragma unroll
            for (int c = 0; c < 4; c++) Bs[kq * 4 + c][bCol[s]] = f[c];
        }
        __syncthreads();
        if (k0 + 16 < kBase + 512) loadT(k0 + 16);
#pragma unroll
        for (int kk = 0; kk < 16; kk++)
            micro_step8(&As[kk][ty * 8], &Bs[kk][tx * 8], acc);
        __syncthreads();
    }

#pragma unroll
    for (int r = 0; r < 8; r++) {
        int row = mBase + ty * 8 + r;
        float* orow = &outp[(size_t)row * LDX + tx * 8];
        float2 v0 = unpack2(acc[r][0]);
        float2 v1 = unpack2(acc[r][1]);
        float2 v2 = unpack2(acc[r][2]);
        float2 v3 = unpack2(acc[r][3]);
        ((float4*)orow)[0] = make_float4(v0.x, v0.y, v1.x, v1.y);
        ((float4*)orow)[1] = make_float4(v2.x, v2.y, v3.x, v3.y);
    }
}

// ============================================================================
// Kernel 1b: combine partials + bias; col150 = 1, cols 151..159 = 0.
// ============================================================================
__global__ __launch_bounds__(256) void proj_combine(
    const float* __restrict__ bS, const float* __restrict__ bE) {
    int idx = blockIdx.x * 256 + threadIdx.x;
    const int TOT = 2 * PROJ_ROWS * (LDX / 4);
    if (idx >= TOT) return;
    int z = idx / (PROJ_ROWS * (LDX / 4));
    int rem = idx % (PROJ_ROWS * (LDX / 4));
    int row = rem / (LDX / 4), cq = rem % (LDX / 4);
    int c0 = cq * 4;
    const float* bias = z ? bE : bS;
    size_t off = (size_t)row * LDX + c0;
    float4 a = *(const float4*)(Pg + (size_t)(z * 2 + 0) * PROJ_ROWS * LDX + off);
    float4 b = *(const float4*)(Pg + (size_t)(z * 2 + 1) * PROJ_ROWS * LDX + off);
    float av[4] = {a.x, a.y, a.z, a.w};
    float bv[4] = {b.x, b.y, b.z, b.w};
    float ov[4];
#pragma unroll
    for (int c = 0; c < 4; c++) {
        int cc = c0 + c;
        ov[c] = (cc < HH) ? av[c] + bv[c] + bias[cc] : (cc == HH ? 1.f : 0.f);
    }
    float* outp = (z ? Yg : Xg) + off;
    *(float4*)outp = make_float4(ov[0], ov[1], ov[2], ov[3]);
}

// ============================================================================
// Kernel 2: Ug[6144][1440] = Xg[6144][160] @ Wpad.
// tile 64x160, block 160, per-thread 8x8, 3 CTA/SM. grid (96, 9).
// ============================================================================
__global__ __launch_bounds__(160, 3) void biaff_left() {
    const int mBase = blockIdx.x * 64;
    const int o = blockIdx.y;
    const float* Wo = Wpad + (size_t)o * LDX * LDX;

    __shared__ alignas(16) float As[16][68];
    __shared__ alignas(16) float Bs[16][164];

    const int t = threadIdx.x;
    const int tx = t % 20, ty = t / 20;

    int aRow[2], aKq[2]; bool aV[2];
#pragma unroll
    for (int s = 0; s < 2; s++) {
        int f = t + 160 * s;
        aV[s] = f < 256; aRow[s] = f >> 2; aKq[s] = f & 3;
    }
    int bKk[4], bJq[4];
#pragma unroll
    for (int s = 0; s < 4; s++) { int f = t + 160 * s; bKk[s] = f / 40; bJq[s] = f % 40; }

    float4 aF[2], bF[4];
    auto loadT = [&](int k0) {
#pragma unroll
        for (int s = 0; s < 2; s++)
            if (aV[s])
                aF[s] = *(const float4*)(Xg + (size_t)(mBase + aRow[s]) * LDX + k0 + aKq[s] * 4);
#pragma unroll
        for (int s = 0; s < 4; s++)
            bF[s] = *(const float4*)(Wo + (size_t)(k0 + bKk[s]) * LDX + bJq[s] * 4);
    };

    unsigned long long acc[8][4];
#pragma unroll
    for (int r = 0; r < 8; r++)
#pragma unroll
        for (int p = 0; p < 4; p++) acc[r][p] = 0ull;

    loadT(0);
    for (int k0 = 0; k0 < LDX; k0 += 16) {
#pragma unroll
        for (int s = 0; s < 2; s++) {
            if (aV[s]) {
                const float* f = (const float*)&aF[s];
#pragma unroll
                for (int c = 0; c < 4; c++) As[aKq[s] * 4 + c][aRow[s]] = f[c];
            }
        }
#pragma unroll
        for (int s = 0; s < 4; s++)
            *(float4*)&Bs[bKk[s]][bJq[s] * 4] = bF[s];
        __syncthreads();
        if (k0 + 16 < LDX) loadT(k0 + 16);
#pragma unroll
        for (int kk = 0; kk < 16; kk++)
            micro_step8(&As[kk][ty * 8], &Bs[kk][tx * 8], acc);
        __syncthreads();
    }

#pragma unroll
    for (int r = 0; r < 8; r++) {
        int row = mBase + ty * 8 + r;
        float* orow = &Ug[(size_t)row * UCOLS + o * LDX + tx * 8];
        float2 v0 = unpack2(acc[r][0]);
        float2 v1 = unpack2(acc[r][1]);
        float2 v2 = unpack2(acc[r][2]);
        float2 v3 = unpack2(acc[r][3]);
        ((float4*)orow)[0] = make_float4(v0.x, v0.y, v1.x, v1.y);
        ((float4*)orow)[1] = make_float4(v2.x, v2.y, v3.x, v3.y);
    }
}

// ============================================================================
// Kernel 3: Sg[b][g][y] (g=x*9+o): C[g][y] = Ug_row(g) · Y[b][y]
// grid (9, 48), block 128, per-thread 16x8.
// ============================================================================
__global__ __launch_bounds__(128, 2) void biaff_right() {
    const int mBase = blockIdx.x * 128;
    const int b = blockIdx.y;
    const float* Yb = &Yg[(size_t)b * LL * LDX];

    __shared__ alignas(16) float As[16][136];
    __shared__ alignas(16) float Bs[16][136];

    const int t = threadIdx.x;
    const int tx = t % 16, ty = t / 16;
    const int kq = t & 3;

    size_t aOff[4];
    int aRow[4];
#pragma unroll
    for (int s = 0; s < 4; s++) {
        int f = t + 128 * s;
        aRow[s] = f >> 2;
        int g = mBase + aRow[s];
        int x = g / 9, oo = g % 9;
        aOff[s] = ((size_t)b * LL + x) * UCOLS + (size_t)oo * LDX;
    }
    int bY[4];
#pragma unroll
    for (int s = 0; s < 4; s++) bY[s] = (t + 128 * s) >> 2;

    float4 aF[4], bF[4];
    auto loadT = [&](int k0) {
#pragma unroll
        for (int s = 0; s < 4; s++)
            aF[s] = *(const float4*)(Ug + aOff[s] + k0 + kq * 4);
#pragma unroll
        for (int s = 0; s < 4; s++)
            bF[s] = *(const float4*)(Yb + (size_t)bY[s] * LDX + k0 + kq * 4);
    };

    unsigned long long acc[16][4];
#pragma unroll
    for (int r = 0; r < 16; r++)
#pragma unroll
        for (int p = 0; p < 4; p++) acc[r][p] = 0ull;

    loadT(0);
    for (int k0 = 0; k0 < LDX; k0 += 16) {
#pragma unroll
        for (int s = 0; s < 4; s++) {
            const float* f = (const float*)&aF[s];
#pragma unroll
            for (int c = 0; c < 4; c++) As[kq * 4 + c][aRow[s]] = f[c];
        }
#pragma unroll
        for (int s = 0; s < 4; s++) {
            const float* f = (const float*)&bF[s];
#pragma unroll
            for (int c = 0; c < 4; c++) Bs[kq * 4 + c][bY[s]] = f[c];
        }
        __syncthreads();
        if (k0 + 16 < LDX) loadT(k0 + 16);
#pragma unroll
        for (int kk = 0; kk < 16; kk++)
            micro_step16(&As[kk][ty * 16], &Bs[kk][tx * 8], acc);
        __syncthreads();
    }

#pragma unroll
    for (int r = 0; r < 16; r++) {
        int g = mBase + ty * 16 + r;
        float* orow = &Sg[((size_t)b * 1152 + g) * LL + tx * 8];
        float2 v0 = unpack2(acc[r][0]);
        float2 v1 = unpack2(acc[r][1]);
        float2 v2 = unpack2(acc[r][2]);
        float2 v3 = unpack2(acc[r][3]);
        ((float4*)orow)[0] = make_float4(v0.x, v0.y, v1.x, v1.y);
        ((float4*)orow)[1] = make_float4(v2.x, v2.y, v3.x, v3.y);
    }
}

// ============================================================================
// Kernel 3b: transpose Sg [b][x][o][y] -> out [b][x][y][o].
// grid 1536, block 256.
// ============================================================================
__global__ __launch_bounds__(256) void transpose_kernel(float* __restrict__ out) {
    __shared__ float tile[4][OO][132];
    const size_t base = (size_t)blockIdx.x * 4 * 1152;
    const float* src = Sg + base;
    for (int e = threadIdx.x; e < 4 * 1152; e += 256) {
        int xr = e / 1152, rem = e % 1152;
        tile[xr][rem >> 7][rem & 127] = src[e];
    }
    __syncthreads();
    float* dst = out + base;
    for (int q = threadIdx.x; q < 4 * 1152; q += 256) {
        int xr = q / 1152, rem = q % 1152;
        int y = rem / 9, o = rem % 9;
        dst[q] = tile[xr][o][y];
    }
}

// ============================================================================
// Kernel 3c: prep — full-chip argmax/key build + result init.
// grid (48, 8), block 256; each block handles 2048 cells of one sentence.
// ============================================================================
__global__ __launch_bounds__(256) void prep_kernel(
    const int* __restrict__ tagseq, float* __restrict__ resOut) {
    const int b = blockIdx.x;
    const int idx0 = blockIdx.y * 2048;
    const float* sB = Sg + (size_t)b * 1152 * LL;  // [x][o][y]
    const int* mB = tagseq + (size_t)b * N_CELLS;
    float* rB = resOut + (size_t)b * N_CELLS;
    unsigned* kB = KeyG + (size_t)b * N_CELLS;
    unsigned char* aB = AnsG + (size_t)b * N_CELLS;

    for (int idx = idx0 + threadIdx.x; idx < idx0 + 2048; idx += 256) {
        int x = idx >> 7, y = idx & 127;
        const float* base = sB + (size_t)x * 1152 + y;
        float best = base[0];
        int bo = 0;
#pragma unroll
        for (int o = 1; o < OO; o++) {
            float v = base[(size_t)o * LL];
            if (v > best) { best = v; bo = o; }
        }
        aB[idx] = (unsigned char)bo;
        bool valid = (bo != 1) && (mB[idx] > 0);
        unsigned u = __float_as_uint(best);
        u ^= (u & 0x80000000u) ? 0xFFFFFFFFu : 0x80000000u;
        unsigned ud = ~u;
        if (!valid) ud = 0xFFFFFFFFu;
        kB[idx] = ud;
        rB[idx] = 1.0f;  // NON_ENTITY
    }
}

// ============================================================================
// Kernel 4: per-sentence greedy decode (radix sort + speculative scan).
// grid 48, block 1024. smem 229504 B. hist[d*32+wrp].
// Phase 1 reduced to coalesced smem fill from KeyG/AnsG.
// ============================================================================
#define DEC_SMEM 229504

__device__ __forceinline__ unsigned long long rmask64(int lo, int hi) {
    unsigned long long m = (hi >= 63) ? ~0ull : ((1ull << (hi + 1)) - 1ull);
    return m & (~0ull << lo);
}

__global__ __launch_bounds__(1024) void decode_kernel(
    float* __restrict__ resOut) {
    const int b = blockIdx.x;
    const int tid = threadIdx.x;
    const int wrp = tid >> 5, lane = tid & 31;
    const unsigned laneLT = (lane == 0) ? 0u : ((1u << lane) - 1u);

    extern __shared__ char smdyn[];
    unsigned* keyA = (unsigned*)(smdyn);
    unsigned* keyB = (unsigned*)(smdyn + 65536);
    unsigned short* payA = (unsigned short*)(smdyn + 131072);
    unsigned short* payB = (unsigned short*)(smdyn + 163840);
    unsigned short* hist = (unsigned short*)(smdyn + 196608);
    unsigned char* ansS = (unsigned char*)(smdyn + 212992);
    unsigned* scanW = (unsigned*)(smdyn + 229376);

    float* rB = resOut + (size_t)b * N_CELLS;
    const unsigned* kB = KeyG + (size_t)b * N_CELLS;
    const uint4* aB4 = (const uint4*)(AnsG + (size_t)b * N_CELLS);

    // ---- Phase 1: coalesced smem fill --------------------------------------
    for (int i = tid; i < N_CELLS; i += 1024) {
        keyA[i] = kB[i];
        payA[i] = (unsigned short)i;
    }
    for (int i = tid; i < N_CELLS / 16; i += 1024)
        ((uint4*)ansS)[i] = aB4[i];
    __syncthreads();

    // ---- Phase 2: stable LSD radix sort, 4x8-bit passes --------------------
    const int chunk = wrp * 512;
#pragma unroll
    for (int pass = 0; pass < 4; pass++) {
        const int shift = pass * 8;
        unsigned* srcK = (pass & 1) ? keyB : keyA;
        unsigned* dstK = (pass & 1) ? keyA : keyB;
        unsigned short* srcP = (pass & 1) ? payB : payA;
        unsigned short* dstP = (pass & 1) ? payA : payB;

        for (int h = tid; h < 8192; h += 1024) hist[h] = 0;
        __syncthreads();

#pragma unroll 4
        for (int r = 0; r < 16; r++) {
            unsigned k = srcK[chunk + r * 32 + lane];
            unsigned d = (k >> shift) & 255u;
            unsigned m = __match_any_sync(FULLMASK, d);
            if ((m & laneLT) == 0)
                hist[d * 32 + wrp] = (unsigned short)(hist[d * 32 + wrp] + __popc(m));
        }
        __syncthreads();

        {
            int h0 = tid * 8;
            unsigned short loc[8];
            unsigned s = 0;
#pragma unroll
            for (int q = 0; q < 8; q++) { loc[q] = hist[h0 + q]; s += loc[q]; }
            unsigned v = s;
#pragma unroll
            for (int off = 1; off < 32; off <<= 1) {
                unsigned n = __shfl_up_sync(FULLMASK, v, off);
                if (lane >= off) v += n;
            }
            if (lane == 31) scanW[wrp] = v;
            __syncthreads();
            if (tid < 32) {
                unsigned wv = scanW[tid];
                unsigned iv = wv;
#pragma unroll
                for (int off = 1; off < 32; off <<= 1) {
                    unsigned n = __shfl_up_sync(FULLMASK, iv, off);
                    if (tid >= off) iv += n;
                }
                scanW[tid] = iv - wv;
            }
            __syncthreads();
            unsigned run = scanW[wrp] + (v - s);
#pragma unroll
            for (int q = 0; q < 8; q++) {
                unsigned c = loc[q];
                hist[h0 + q] = (unsigned short)run;
                run += c;
            }
        }
        __syncthreads();

#pragma unroll 4
        for (int r = 0; r < 16; r++) {
            int idx = chunk + r * 32 + lane;
            unsigned k = srcK[idx];
            unsigned short p = srcP[idx];
            unsigned d = (k >> shift) & 255u;
            unsigned m = __match_any_sync(FULLMASK, d);
            int rank = __popc(m & laneLT);
            int leaderLane = __ffs(m) - 1;
            unsigned baseOff = 0;
            if (lane == leaderLane) {
                baseOff = hist[d * 32 + wrp];
                hist[d * 32 + wrp] = (unsigned short)(baseOff + __popc(m));
            }
            baseOff = __shfl_sync(FULLMASK, baseOff, leaderLane);
            dstK[baseOff + rank] = k;
            dstP[baseOff + rank] = p;
        }
        __syncthreads();
    }

    // ---- Phase 3: warp 0 speculative greedy scan, 64-item windows ----------
    if (tid < 32) {
        unsigned long long st0 = 0, st1 = 0, cv0 = 0, cv1 = 0;
        int t = 0;
        while (t < N_CELLS) {
            int myA = t + lane, myB = t + 32 + lane;
            unsigned udA = (myA < N_CELLS) ? keyA[myA] : 0xFFFFFFFFu;
            unsigned udB = (myB < N_CELLS) ? keyA[myB] : 0xFFFFFFFFu;
            int idxA = (myA < N_CELLS) ? (int)payA[myA] : 0;
            int idxB = (myB < N_CELLS) ? (int)payA[myB] : 0;
            bool valA = (udA != 0xFFFFFFFFu);
            bool valB = (udB != 0xFFFFFFFFu);
            int iA = idxA >> 7, jA = idxA & 127;
            int iB = idxB >> 7, jB = idxB & 127;
            int avA = (int)ansS[idxA];
            int avB = (int)ansS[idxB];

            bool upA = (jA >= iA), upB = (jB >= iB);
            unsigned long long sA0 = 0, sA1 = 0, sB0 = 0, sB1 = 0;
            if (upA) {
                if (iA <= 63) sA0 = rmask64(iA, jA < 63 ? jA : 63);
                if (jA >= 64) sA1 = rmask64(iA > 64 ? iA - 64 : 0, jA - 64);
            }
            if (upB) {
                if (iB <= 63) sB0 = rmask64(iB, jB < 63 ? jB : 63);
                if (jB >= 64) sB1 = rmask64(iB > 64 ? iB - 64 : 0, jB - 64);
            }
            bool stA = (iA < 64) ? ((st0 >> iA) & 1ull) : ((st1 >> (iA - 64)) & 1ull);
            bool cvA = (iA < 64) ? ((cv0 >> iA) & 1ull) : ((cv1 >> (iA - 64)) & 1ull);
            bool stB = (iB < 64) ? ((st0 >> iB) & 1ull) : ((st1 >> (iB - 64)) & 1ull);
            bool cvB = (iB < 64) ? ((cv0 >> iB) & 1ull) : ((cv1 >> (iB - 64)) & 1ull);
            bool accA = valA && !((((st0 & sA0) | (st1 & sA1)) != 0ull) || cvA);
            bool accB = valB && !((((st0 & sB0) | (st1 & sB1)) != 0ull) || cvB);
            bool schgA = accA && (upA || !stA);
            bool schgB = accB && (upB || !stB);

            unsigned long long bInv =
                (unsigned long long)__ballot_sync(FULLMASK, !valA) |
                ((unsigned long long)__ballot_sync(FULLMASK, !valB) << 32);
            unsigned long long bS =
                (unsigned long long)__ballot_sync(FULLMASK, schgA) |
                ((unsigned long long)__ballot_sync(FULLMASK, schgB) << 32);
            int fI = bInv ? (__ffsll((long long)bInv) - 1) : 64;
            if (fI < 64) bS &= (fI ? ((1ull << fI) - 1ull) : 0ull);
            int fS = bS ? (__ffsll((long long)bS) - 1) : 64;
            int lim = fS < fI ? fS : fI;

            if (accA && lane < lim) rB[idxA] = (float)avA;
            if (accB && 32 + lane < lim) rB[idxB] = (float)avB;

            if (fS < fI && fS < 64) {
                int sl = fS & 31;
                bool second = fS >= 32;
                if (lane == sl) {
                    int i = second ? iB : iA;
                    bool up = second ? upB : upA;
                    unsigned long long p0 = second ? sB0 : sA0;
                    unsigned long long p1 = second ? sB1 : sA1;
                    rB[second ? idxB : idxA] = (float)(second ? avB : avA);
                    if (i < 64) st0 |= (1ull << i); else st1 |= (1ull << (i - 64));
                    if (up) { cv0 |= p0; cv1 |= p1; }
                }
                st0 = __shfl_sync(FULLMASK, st0, sl);
                st1 = __shfl_sync(FULLMASK, st1, sl);
                cv0 = __shfl_sync(FULLMASK, cv0, sl);
                cv1 = __shfl_sync(FULLMASK, cv1, sl);
                t += fS + 1;
            } else if (fI < 64) {
                break;
            } else {
                t += 64;
            }
        }
    }
}

// ============================================================================
extern "C" void kernel_launch(void* const* d_in, const int* in_sizes, int n_in,
                              void* d_out, int out_size) {
    (void)in_sizes; (void)n_in;
    const float* bert = (const float*)d_in[0];
    const int*   tagseq = (const int*)d_in[1];
    const float* wS = (const float*)d_in[2];
    const float* bS = (const float*)d_in[3];
    const float* wE = (const float*)d_in[4];
    const float* bE = (const float*)d_in[5];
    const float* Wb = (const float*)d_in[6];
    float* out = (float*)d_out;

    // lazy one-time resource setup (no device memory allocation)
    static cudaStream_t s1 = nullptr;
    static cudaEvent_t evRoot = nullptr, evPad = nullptr, evS = nullptr, evT = nullptr;
    if (s1 == nullptr) {
        cudaStreamCreateWithFlags(&s1, cudaStreamNonBlocking);
        cudaEventCreateWithFlags(&evRoot, cudaEventDisableTiming);
        cudaEventCreateWithFlags(&evPad, cudaEventDisableTiming);
        cudaEventCreateWithFlags(&evS, cudaEventDisableTiming);
        cudaEventCreateWithFlags(&evT, cudaEventDisableTiming);
        cudaFuncSetAttribute(decode_kernel,
                             cudaFuncAttributeMaxDynamicSharedMemorySize, DEC_SMEM);
    }

    // fork s1 from the main (capture) stream
    cudaEventRecord(evRoot, 0);
    cudaStreamWaitEvent(s1, evRoot, 0);

    // s1: pad_w  (overlaps proj_partial on s0; biaff_left waits on it)
    pad_w_kernel<<<(OO * LDX * LDX + 255) / 256, 256, 0, s1>>>(Wb);
    cudaEventRecord(evPad, s1);

    // s0: main pipeline
    proj_partial<<<dim3(96, 2, 2), 160>>>(bert, wS, wE);
    proj_combine<<<(2 * PROJ_ROWS * (LDX / 4) + 255) / 256, 256>>>(bS, bE);
    cudaStreamWaitEvent(0, evPad, 0);
    biaff_left<<<dim3(96, 9), 160>>>();
    biaff_right<<<dim3(9, 48), 128>>>();
    cudaEventRecord(evS, 0);

    bool scoreInOut = (out_size >= SCORE_ELEMS);
    bool didT = false;
    if (scoreInOut) {
        // s1: transpose overlaps prep+decode
        cudaStreamWaitEvent(s1, evS, 0);
        transpose_kernel<<<1536, 256, 0, s1>>>(out);
        cudaEventRecord(evT, s1);
        didT = true;
    }

    float* resPtr = nullptr;
    if (out_size >= SCORE_ELEMS + RESULT_ELEMS) resPtr = out + SCORE_ELEMS;
    else if (!scoreInOut && out_size >= RESULT_ELEMS) resPtr = out;

    if (resPtr) {
        // full-chip prep (argmax/keys/result-init), then per-sentence decode
        prep_kernel<<<dim3(48, 8), 256>>>(tagseq, resPtr);
        decode_kernel<<<48, 1024, DEC_SMEM>>>(resPtr);
    }

    // join s1 back into the capture stream
    if (didT) cudaStreamWaitEvent(0, evT, 0);
}

// round 13
// speedup vs baseline: 1.0271x; 1.0271x over previous
#include <cuda_runtime.h>
#include <cstdint>

// Problem constants
#define BB 48
#define LL 128
#define DD 1024
#define HH 150      // ffnn out
#define HP 151      // +bias col
#define OO 9
#define LDX 160     // padded feature stride

#define N_CELLS (LL*LL)              // 16384
#define SCORE_ELEMS (BB*LL*LL*OO)    // 7077888
#define RESULT_ELEMS (BB*LL*LL)      // 786432
#define UCOLS (OO*LDX)               // 1440
#define PROJ_ROWS (BB*LL)            // 6144

#define FULLMASK 0xFFFFFFFFu

// ---------------- static device scratch --------------------------------------
__device__ float Xg[(size_t)PROJ_ROWS*LDX];           // [6144][160]
__device__ float Yg[(size_t)PROJ_ROWS*LDX];
__device__ float Pg[(size_t)4*PROJ_ROWS*LDX];         // split-K partials [side*2+half]
__device__ float Ug[(size_t)BB*LL*UCOLS];             // [6144][1440]
__device__ float Sg[(size_t)SCORE_ELEMS];             // [b][x][o][y]
__device__ float Wpad[(size_t)OO*LDX*LDX];            // [9][160][160]

// ---------------- f32x2 helpers ---------------------------------------------
__device__ __forceinline__ void fma2(unsigned long long& d, unsigned long long a,
                                     unsigned long long b) {
    asm("fma.rn.f32x2 %0, %1, %2, %0;" : "+l"(d) : "l"(a), "l"(b));
}
__device__ __forceinline__ unsigned long long pack2(float x) {
    unsigned long long r;
    asm("mov.b64 %0, {%1, %1};" : "=l"(r) : "f"(x));
    return r;
}
__device__ __forceinline__ float2 unpack2(unsigned long long v) {
    float2 f;
    asm("mov.b64 {%0, %1}, %2;" : "=f"(f.x), "=f"(f.y) : "l"(v));
    return f;
}

// 8-row x 8-col micro step
__device__ __forceinline__ void micro_step8(const float* __restrict__ aRow,
                                            const float* __restrict__ bRow,
                                            unsigned long long acc[8][4]) {
    float4 a0 = *(const float4*)(aRow);
    float4 a1 = *(const float4*)(aRow + 4);
    ulonglong2 q0 = *(const ulonglong2*)(bRow);
    ulonglong2 q1 = *(const ulonglong2*)(bRow + 4);
    unsigned long long bb[4] = {q0.x, q0.y, q1.x, q1.y};
    float av[8] = {a0.x, a0.y, a0.z, a0.w, a1.x, a1.y, a1.z, a1.w};
#pragma unroll
    for (int r = 0; r < 8; r++) {
        unsigned long long ap = pack2(av[r]);
#pragma unroll
        for (int p = 0; p < 4; p++) fma2(acc[r][p], ap, bb[p]);
    }
}

// 16-row x 8-col micro step
__device__ __forceinline__ void micro_step16(const float* __restrict__ aRow,
                                             const float* __restrict__ bRow,
                                             unsigned long long acc[16][4]) {
    float4 a0 = *(const float4*)(aRow);
    float4 a1 = *(const float4*)(aRow + 4);
    float4 a2 = *(const float4*)(aRow + 8);
    float4 a3 = *(const float4*)(aRow + 12);
    ulonglong2 q0 = *(const ulonglong2*)(bRow);
    ulonglong2 q1 = *(const ulonglong2*)(bRow + 4);
    unsigned long long bb[4] = {q0.x, q0.y, q1.x, q1.y};
    float av[16] = {a0.x, a0.y, a0.z, a0.w, a1.x, a1.y, a1.z, a1.w,
                    a2.x, a2.y, a2.z, a2.w, a3.x, a3.y, a3.z, a3.w};
#pragma unroll
    for (int r = 0; r < 16; r++) {
        unsigned long long ap = pack2(av[r]);
#pragma unroll
        for (int p = 0; p < 4; p++) fma2(acc[r][p], ap, bb[p]);
    }
}

// ============================================================================
// Kernel 0: pad W [9][151][151] -> Wpad [9][160][160] (zeros elsewhere)
// ============================================================================
__global__ __launch_bounds__(256) void pad_w_kernel(const float* __restrict__ Wb) {
    int idx = blockIdx.x * 256 + threadIdx.x;
    if (idx >= OO * LDX * LDX) return;
    int o = idx / (LDX * LDX);
    int r = idx % (LDX * LDX);
    int i = r / LDX, j = r % LDX;
    Wpad[idx] = (i < HP && j < HP) ? Wb[(size_t)o * HP * HP + i * HP + j] : 0.f;
}

// ============================================================================
// Kernel 1a: split-K projection partials.
// grid (96, 2, 2): x = 64-row tile, y = side (X/Y), z = K half (512 each).
// ============================================================================
__global__ __launch_bounds__(160, 3) void proj_partial(
    const float* __restrict__ bert,
    const float* __restrict__ wS, const float* __restrict__ wE) {
    const int z = blockIdx.y;
    const int h = blockIdx.z;
    const float* w = z ? wE : wS;
    float* outp = Pg + (size_t)(z * 2 + h) * PROJ_ROWS * LDX;
    const int mBase = blockIdx.x * 64;
    const int kBase = h * 512;

    __shared__ alignas(16) float As[16][72];
    __shared__ alignas(16) float Bs[16][168];

    const int t = threadIdx.x;
    const int tx = t % 20, ty = t / 20;

    const int aRow0 = t >> 2, aRow1 = (t + 160) >> 2;
    const bool aV1 = (t < 96);
    const int kq = t & 3;
    int bCol[4];
#pragma unroll
    for (int s = 0; s < 4; s++) bCol[s] = (t + 160 * s) >> 2;

    float4 aF[2], bF[4];
    const float4 z4 = make_float4(0.f, 0.f, 0.f, 0.f);
    auto loadT = [&](int k0) {
        aF[0] = *(const float4*)(bert + (size_t)(mBase + aRow0) * DD + k0 + kq * 4);
        aF[1] = aV1 ? *(const float4*)(bert + (size_t)(mBase + aRow1) * DD + k0 + kq * 4) : z4;
#pragma unroll
        for (int s = 0; s < 4; s++)
            bF[s] = (bCol[s] < HH)
                  ? *(const float4*)(w + (size_t)bCol[s] * DD + k0 + kq * 4) : z4;
    };

    unsigned long long acc[8][4];
#pragma unroll
    for (int r = 0; r < 8; r++)
#pragma unroll
        for (int p = 0; p < 4; p++) acc[r][p] = 0ull;

    loadT(kBase);
    for (int k0 = kBase; k0 < kBase + 512; k0 += 16) {
        {
            const float* f = (const float*)&aF[0];
#pragma unroll
            for (int c = 0; c < 4; c++) As[kq * 4 + c][aRow0] = f[c];
        }
        if (aV1) {
            const float* f = (const float*)&aF[1];
#pragma unroll
            for (int c = 0; c < 4; c++) As[kq * 4 + c][aRow1] = f[c];
        }
#pragma unroll
        for (int s = 0; s < 4; s++) {
            const float* f = (const float*)&bF[s];
#pragma unroll
            for (int c = 0; c < 4; c++) Bs[kq * 4 + c][bCol[s]] = f[c];
        }
        __syncthreads();
        if (k0 + 16 < kBase + 512) loadT(k0 + 16);
#pragma unroll
        for (int kk = 0; kk < 16; kk++)
            micro_step8(&As[kk][ty * 8], &Bs[kk][tx * 8], acc);
        __syncthreads();
    }

#pragma unroll
    for (int r = 0; r < 8; r++) {
        int row = mBase + ty * 8 + r;
        float* orow = &outp[(size_t)row * LDX + tx * 8];
        float2 v0 = unpack2(acc[r][0]);
        float2 v1 = unpack2(acc[r][1]);
        float2 v2 = unpack2(acc[r][2]);
        float2 v3 = unpack2(acc[r][3]);
        ((float4*)orow)[0] = make_float4(v0.x, v0.y, v1.x, v1.y);
        ((float4*)orow)[1] = make_float4(v2.x, v2.y, v3.x, v3.y);
    }
}

// ============================================================================
// Kernel 1b: combine partials + bias; col150 = 1, cols 151..159 = 0.
// ============================================================================
__global__ __launch_bounds__(256) void proj_combine(
    const float* __restrict__ bS, const float* __restrict__ bE) {
    int idx = blockIdx.x * 256 + threadIdx.x;
    const int TOT = 2 * PROJ_ROWS * (LDX / 4);
    if (idx >= TOT) return;
    int z = idx / (PROJ_ROWS * (LDX / 4));
    int rem = idx % (PROJ_ROWS * (LDX / 4));
    int row = rem / (LDX / 4), cq = rem % (LDX / 4);
    int c0 = cq * 4;
    const float* bias = z ? bE : bS;
    size_t off = (size_t)row * LDX + c0;
    float4 a = *(const float4*)(Pg + (size_t)(z * 2 + 0) * PROJ_ROWS * LDX + off);
    float4 b = *(const float4*)(Pg + (size_t)(z * 2 + 1) * PROJ_ROWS * LDX + off);
    float av[4] = {a.x, a.y, a.z, a.w};
    float bv[4] = {b.x, b.y, b.z, b.w};
    float ov[4];
#pragma unroll
    for (int c = 0; c < 4; c++) {
        int cc = c0 + c;
        ov[c] = (cc < HH) ? av[c] + bv[c] + bias[cc] : (cc == HH ? 1.f : 0.f);
    }
    float* outp = (z ? Yg : Xg) + off;
    *(float4*)outp = make_float4(ov[0], ov[1], ov[2], ov[3]);
}

// ============================================================================
// Kernel 2: Ug[6144][1440] = Xg[6144][160] @ Wpad.
// tile 64x160, block 160, per-thread 8x8, 3 CTA/SM. grid (96, 9).
// ============================================================================
__global__ __launch_bounds__(160, 3) void biaff_left() {
    const int mBase = blockIdx.x * 64;
    const int o = blockIdx.y;
    const float* Wo = Wpad + (size_t)o * LDX * LDX;

    __shared__ alignas(16) float As[16][68];
    __shared__ alignas(16) float Bs[16][164];

    const int t = threadIdx.x;
    const int tx = t % 20, ty = t / 20;

    int aRow[2], aKq[2]; bool aV[2];
#pragma unroll
    for (int s = 0; s < 2; s++) {
        int f = t + 160 * s;
        aV[s] = f < 256; aRow[s] = f >> 2; aKq[s] = f & 3;
    }
    int bKk[4], bJq[4];
#pragma unroll
    for (int s = 0; s < 4; s++) { int f = t + 160 * s; bKk[s] = f / 40; bJq[s] = f % 40; }

    float4 aF[2], bF[4];
    auto loadT = [&](int k0) {
#pragma unroll
        for (int s = 0; s < 2; s++)
            if (aV[s])
                aF[s] = *(const float4*)(Xg + (size_t)(mBase + aRow[s]) * LDX + k0 + aKq[s] * 4);
#pragma unroll
        for (int s = 0; s < 4; s++)
            bF[s] = *(const float4*)(Wo + (size_t)(k0 + bKk[s]) * LDX + bJq[s] * 4);
    };

    unsigned long long acc[8][4];
#pragma unroll
    for (int r = 0; r < 8; r++)
#pragma unroll
        for (int p = 0; p < 4; p++) acc[r][p] = 0ull;

    loadT(0);
    for (int k0 = 0; k0 < LDX; k0 += 16) {
#pragma unroll
        for (int s = 0; s < 2; s++) {
            if (aV[s]) {
                const float* f = (const float*)&aF[s];
#pragma unroll
                for (int c = 0; c < 4; c++) As[aKq[s] * 4 + c][aRow[s]] = f[c];
            }
        }
#pragma unroll
        for (int s = 0; s < 4; s++)
            *(float4*)&Bs[bKk[s]][bJq[s] * 4] = bF[s];
        __syncthreads();
        if (k0 + 16 < LDX) loadT(k0 + 16);
#pragma unroll
        for (int kk = 0; kk < 16; kk++)
            micro_step8(&As[kk][ty * 8], &Bs[kk][tx * 8], acc);
        __syncthreads();
    }

#pragma unroll
    for (int r = 0; r < 8; r++) {
        int row = mBase + ty * 8 + r;
        float* orow = &Ug[(size_t)row * UCOLS + o * LDX + tx * 8];
        float2 v0 = unpack2(acc[r][0]);
        float2 v1 = unpack2(acc[r][1]);
        float2 v2 = unpack2(acc[r][2]);
        float2 v3 = unpack2(acc[r][3]);
        ((float4*)orow)[0] = make_float4(v0.x, v0.y, v1.x, v1.y);
        ((float4*)orow)[1] = make_float4(v2.x, v2.y, v3.x, v3.y);
    }
}

// ============================================================================
// Kernel 3: Sg[b][g][y] (g=x*9+o): C[g][y] = Ug_row(g) · Y[b][y]
// grid (9, 48), block 128, per-thread 16x8.
// ============================================================================
__global__ __launch_bounds__(128, 2) void biaff_right() {
    const int mBase = blockIdx.x * 128;
    const int b = blockIdx.y;
    const float* Yb = &Yg[(size_t)b * LL * LDX];

    __shared__ alignas(16) float As[16][136];
    __shared__ alignas(16) float Bs[16][136];

    const int t = threadIdx.x;
    const int tx = t % 16, ty = t / 16;
    const int kq = t & 3;

    size_t aOff[4];
    int aRow[4];
#pragma unroll
    for (int s = 0; s < 4; s++) {
        int f = t + 128 * s;
        aRow[s] = f >> 2;
        int g = mBase + aRow[s];
        int x = g / 9, oo = g % 9;
        aOff[s] = ((size_t)b * LL + x) * UCOLS + (size_t)oo * LDX;
    }
    int bY[4];
#pragma unroll
    for (int s = 0; s < 4; s++) bY[s] = (t + 128 * s) >> 2;

    float4 aF[4], bF[4];
    auto loadT = [&](int k0) {
#pragma unroll
        for (int s = 0; s < 4; s++)
            aF[s] = *(const float4*)(Ug + aOff[s] + k0 + kq * 4);
#pragma unroll
        for (int s = 0; s < 4; s++)
            bF[s] = *(const float4*)(Yb + (size_t)bY[s] * LDX + k0 + kq * 4);
    };

    unsigned long long acc[16][4];
#pragma unroll
    for (int r = 0; r < 16; r++)
#pragma unroll
        for (int p = 0; p < 4; p++) acc[r][p] = 0ull;

    loadT(0);
    for (int k0 = 0; k0 < LDX; k0 += 16) {
#pragma unroll
        for (int s = 0; s < 4; s++) {
            const float* f = (const float*)&aF[s];
#pragma unroll
            for (int c = 0; c < 4; c++) As[kq * 4 + c][aRow[s]] = f[c];
        }
#pragma unroll
        for (int s = 0; s < 4; s++) {
            const float* f = (const float*)&bF[s];
#pragma unroll
            for (int c = 0; c < 4; c++) Bs[kq * 4 + c][bY[s]] = f[c];
        }
        __syncthreads();
        if (k0 + 16 < LDX) loadT(k0 + 16);
#pragma unroll
        for (int kk = 0; kk < 16; kk++)
            micro_step16(&As[kk][ty * 16], &Bs[kk][tx * 8], acc);
        __syncthreads();
    }

#pragma unroll
    for (int r = 0; r < 16; r++) {
        int g = mBase + ty * 16 + r;
        float* orow = &Sg[((size_t)b * 1152 + g) * LL + tx * 8];
        float2 v0 = unpack2(acc[r][0]);
        float2 v1 = unpack2(acc[r][1]);
        float2 v2 = unpack2(acc[r][2]);
        float2 v3 = unpack2(acc[r][3]);
        ((float4*)orow)[0] = make_float4(v0.x, v0.y, v1.x, v1.y);
        ((float4*)orow)[1] = make_float4(v2.x, v2.y, v3.x, v3.y);
    }
}

// ============================================================================
// Kernel 3b: transpose Sg [b][x][o][y] -> out [b][x][y][o].
// grid 1536, block 256.
// ============================================================================
__global__ __launch_bounds__(256) void transpose_kernel(float* __restrict__ out) {
    __shared__ float tile[4][OO][132];
    const size_t base = (size_t)blockIdx.x * 4 * 1152;
    const float* src = Sg + base;
    for (int e = threadIdx.x; e < 4 * 1152; e += 256) {
        int xr = e / 1152, rem = e % 1152;
        tile[xr][rem >> 7][rem & 127] = src[e];
    }
    __syncthreads();
    float* dst = out + base;
    for (int q = threadIdx.x; q < 4 * 1152; q += 256) {
        int xr = q / 1152, rem = q % 1152;
        int y = rem / 9, o = rem % 9;
        dst[q] = tile[xr][o][y];
    }
}

// ============================================================================
// Kernel 4: per-sentence greedy decode (radix sort + speculative scan).
// grid 48, block 1024. smem 229504 B.
// hist layout: hist[wrp*256 + d] -> bank = (d>>1)%32 (~2-way conflicts in
// count/scatter vs 16-way with the old d*32+wrp layout).
// ============================================================================
#define DEC_SMEM 229504

__device__ __forceinline__ unsigned long long rmask64(int lo, int hi) {
    unsigned long long m = (hi >= 63) ? ~0ull : ((1ull << (hi + 1)) - 1ull);
    return m & (~0ull << lo);
}

__global__ __launch_bounds__(1024) void decode_kernel(
    const int* __restrict__ tagseq,
    float* __restrict__ resOut) {
    const int b = blockIdx.x;
    const int tid = threadIdx.x;
    const int wrp = tid >> 5, lane = tid & 31;
    const unsigned laneLT = (lane == 0) ? 0u : ((1u << lane) - 1u);

    extern __shared__ char smdyn[];
    unsigned* keyA = (unsigned*)(smdyn);
    unsigned* keyB = (unsigned*)(smdyn + 65536);
    unsigned short* payA = (unsigned short*)(smdyn + 131072);
    unsigned short* payB = (unsigned short*)(smdyn + 163840);
    unsigned short* hist = (unsigned short*)(smdyn + 196608);
    unsigned char* ansS = (unsigned char*)(smdyn + 212992);
    unsigned* scanW = (unsigned*)(smdyn + 229376);

    const float* sB = Sg + (size_t)b * 1152 * LL;  // [x][o][y]
    const int* mB = tagseq + (size_t)b * N_CELLS;
    float* rB = resOut + (size_t)b * N_CELLS;

    // ---- Phase 1: argmax over O, keys, result init -------------------------
    for (int idx = tid; idx < N_CELLS; idx += 1024) {
        int x = idx >> 7, y = idx & 127;
        const float* base = sB + (size_t)x * 1152 + y;
        float best = base[0];
        int bo = 0;
#pragma unroll
        for (int o = 1; o < OO; o++) {
            float v = base[(size_t)o * LL];
            if (v > best) { best = v; bo = o; }
        }
        ansS[idx] = (unsigned char)bo;
        bool valid = (bo != 1) && (mB[idx] > 0);
        unsigned u = __float_as_uint(best);
        u ^= (u & 0x80000000u) ? 0xFFFFFFFFu : 0x80000000u;
        unsigned ud = ~u;
        if (!valid) ud = 0xFFFFFFFFu;
        keyA[idx] = ud;
        payA[idx] = (unsigned short)idx;
        rB[idx] = 1.0f;
    }
    __syncthreads();

    // ---- Phase 2: stable LSD radix sort, 4x8-bit passes --------------------
    const int chunk = wrp * 512;
#pragma unroll
    for (int pass = 0; pass < 4; pass++) {
        const int shift = pass * 8;
        unsigned* srcK = (pass & 1) ? keyB : keyA;
        unsigned* dstK = (pass & 1) ? keyA : keyB;
        unsigned short* srcP = (pass & 1) ? payB : payA;
        unsigned short* dstP = (pass & 1) ? payA : payB;

        for (int h = tid; h < 8192; h += 1024) hist[h] = 0;
        __syncthreads();

        // count (bank-spread layout)
#pragma unroll 4
        for (int r = 0; r < 16; r++) {
            unsigned k = srcK[chunk + r * 32 + lane];
            unsigned d = (k >> shift) & 255u;
            unsigned m = __match_any_sync(FULLMASK, d);
            if ((m & laneLT) == 0)
                hist[wrp * 256 + d] = (unsigned short)(hist[wrp * 256 + d] + __popc(m));
        }
        __syncthreads();

        // exclusive scan in logical order p = d*32 + w over hist[w*256+d]
        {
            const int p0 = tid * 8;
            const int dScan = p0 >> 5;            // digit constant within octet
            const int wBase = p0 & 31;            // (tid%4)*8
            unsigned short loc[8];
            unsigned s = 0;
#pragma unroll
            for (int q = 0; q < 8; q++) {
                loc[q] = hist[(wBase + q) * 256 + dScan];
                s += loc[q];
            }
            unsigned v = s;
#pragma unroll
            for (int off = 1; off < 32; off <<= 1) {
                unsigned n = __shfl_up_sync(FULLMASK, v, off);
                if (lane >= off) v += n;
            }
            if (lane == 31) scanW[wrp] = v;
            __syncthreads();
            if (tid < 32) {
                unsigned wv = scanW[tid];
                unsigned iv = wv;
#pragma unroll
                for (int off = 1; off < 32; off <<= 1) {
                    unsigned n = __shfl_up_sync(FULLMASK, iv, off);
                    if (tid >= off) iv += n;
                }
                scanW[tid] = iv - wv;
            }
            __syncthreads();
            unsigned run = scanW[wrp] + (v - s);
#pragma unroll
            for (int q = 0; q < 8; q++) {
                unsigned c = loc[q];
                hist[(wBase + q) * 256 + dScan] = (unsigned short)run;
                run += c;
            }
        }
        __syncthreads();

        // scatter (bank-spread layout)
#pragma unroll 4
        for (int r = 0; r < 16; r++) {
            int idx = chunk + r * 32 + lane;
            unsigned k = srcK[idx];
            unsigned short p = srcP[idx];
            unsigned d = (k >> shift) & 255u;
            unsigned m = __match_any_sync(FULLMASK, d);
            int rank = __popc(m & laneLT);
            int leaderLane = __ffs(m) - 1;
            unsigned baseOff = 0;
            if (lane == leaderLane) {
                baseOff = hist[wrp * 256 + d];
                hist[wrp * 256 + d] = (unsigned short)(baseOff + __popc(m));
            }
            baseOff = __shfl_sync(FULLMASK, baseOff, leaderLane);
            dstK[baseOff + rank] = k;
            dstP[baseOff + rank] = p;
        }
        __syncthreads();
    }

    // ---- Phase 3: warp 0 speculative greedy scan, 64-item windows ----------
    if (tid < 32) {
        unsigned long long st0 = 0, st1 = 0, cv0 = 0, cv1 = 0;
        int t = 0;
        while (t < N_CELLS) {
            int myA = t + lane, myB = t + 32 + lane;
            unsigned udA = (myA < N_CELLS) ? keyA[myA] : 0xFFFFFFFFu;
            unsigned udB = (myB < N_CELLS) ? keyA[myB] : 0xFFFFFFFFu;
            int idxA = (myA < N_CELLS) ? (int)payA[myA] : 0;
            int idxB = (myB < N_CELLS) ? (int)payA[myB] : 0;
            bool valA = (udA != 0xFFFFFFFFu);
            bool valB = (udB != 0xFFFFFFFFu);
            int iA = idxA >> 7, jA = idxA & 127;
            int iB = idxB >> 7, jB = idxB & 127;
            int avA = (int)ansS[idxA];
            int avB = (int)ansS[idxB];

            bool upA = (jA >= iA), upB = (jB >= iB);
            unsigned long long sA0 = 0, sA1 = 0, sB0 = 0, sB1 = 0;
            if (upA) {
                if (iA <= 63) sA0 = rmask64(iA, jA < 63 ? jA : 63);
                if (jA >= 64) sA1 = rmask64(iA > 64 ? iA - 64 : 0, jA - 64);
            }
            if (upB) {
                if (iB <= 63) sB0 = rmask64(iB, jB < 63 ? jB : 63);
                if (jB >= 64) sB1 = rmask64(iB > 64 ? iB - 64 : 0, jB - 64);
            }
            bool stA = (iA < 64) ? ((st0 >> iA) & 1ull) : ((st1 >> (iA - 64)) & 1ull);
            bool cvA = (iA < 64) ? ((cv0 >> iA) & 1ull) : ((cv1 >> (iA - 64)) & 1ull);
            bool stB = (iB < 64) ? ((st0 >> iB) & 1ull) : ((st1 >> (iB - 64)) & 1ull);
            bool cvB = (iB < 64) ? ((cv0 >> iB) & 1ull) : ((cv1 >> (iB - 64)) & 1ull);
            bool accA = valA && !((((st0 & sA0) | (st1 & sA1)) != 0ull) || cvA);
            bool accB = valB && !((((st0 & sB0) | (st1 & sB1)) != 0ull) || cvB);
            bool schgA = accA && (upA || !stA);
            bool schgB = accB && (upB || !stB);

            unsigned long long bInv =
                (unsigned long long)__ballot_sync(FULLMASK, !valA) |
                ((unsigned long long)__ballot_sync(FULLMASK, !valB) << 32);
            unsigned long long bS =
                (unsigned long long)__ballot_sync(FULLMASK, schgA) |
                ((unsigned long long)__ballot_sync(FULLMASK, schgB) << 32);
            int fI = bInv ? (__ffsll((long long)bInv) - 1) : 64;
            if (fI < 64) bS &= (fI ? ((1ull << fI) - 1ull) : 0ull);
            int fS = bS ? (__ffsll((long long)bS) - 1) : 64;
            int lim = fS < fI ? fS : fI;

            if (accA && lane < lim) rB[idxA] = (float)avA;
            if (accB && 32 + lane < lim) rB[idxB] = (float)avB;

            if (fS < fI && fS < 64) {
                int sl = fS & 31;
                bool second = fS >= 32;
                if (lane == sl) {
                    int i = second ? iB : iA;
                    bool up = second ? upB : upA;
                    unsigned long long p0 = second ? sB0 : sA0;
                    unsigned long long p1 = second ? sB1 : sA1;
                    rB[second ? idxB : idxA] = (float)(second ? avB : avA);
                    if (i < 64) st0 |= (1ull << i); else st1 |= (1ull << (i - 64));
                    if (up) { cv0 |= p0; cv1 |= p1; }
                }
                st0 = __shfl_sync(FULLMASK, st0, sl);
                st1 = __shfl_sync(FULLMASK, st1, sl);
                cv0 = __shfl_sync(FULLMASK, cv0, sl);
                cv1 = __shfl_sync(FULLMASK, cv1, sl);
                t += fS + 1;
            } else if (fI < 64) {
                break;
            } else {
                t += 64;
            }
        }
    }
}

// ============================================================================
extern "C" void kernel_launch(void* const* d_in, const int* in_sizes, int n_in,
                              void* d_out, int out_size) {
    (void)in_sizes; (void)n_in;
    const float* bert = (const float*)d_in[0];
    const int*   tagseq = (const int*)d_in[1];
    const float* wS = (const float*)d_in[2];
    const float* bS = (const float*)d_in[3];
    const float* wE = (const float*)d_in[4];
    const float* bE = (const float*)d_in[5];
    const float* Wb = (const float*)d_in[6];
    float* out = (float*)d_out;

    // lazy one-time resource setup (no device memory allocation)
    static cudaStream_t s1 = nullptr;
    static cudaEvent_t evRoot = nullptr, evPad = nullptr, evS = nullptr, evT = nullptr;
    if (s1 == nullptr) {
        cudaStreamCreateWithFlags(&s1, cudaStreamNonBlocking);
        cudaEventCreateWithFlags(&evRoot, cudaEventDisableTiming);
        cudaEventCreateWithFlags(&evPad, cudaEventDisableTiming);
        cudaEventCreateWithFlags(&evS, cudaEventDisableTiming);
        cudaEventCreateWithFlags(&evT, cudaEventDisableTiming);
        cudaFuncSetAttribute(decode_kernel,
                             cudaFuncAttributeMaxDynamicSharedMemorySize, DEC_SMEM);
    }

    // fork s1 from the main (capture) stream
    cudaEventRecord(evRoot, 0);
    cudaStreamWaitEvent(s1, evRoot, 0);

    // s1: pad_w  (overlaps proj_partial on s0; biaff_left waits on it)
    pad_w_kernel<<<(OO * LDX * LDX + 255) / 256, 256, 0, s1>>>(Wb);
    cudaEventRecord(evPad, s1);

    // s0: main pipeline
    proj_partial<<<dim3(96, 2, 2), 160>>>(bert, wS, wE);
    proj_combine<<<(2 * PROJ_ROWS * (LDX / 4) + 255) / 256, 256>>>(bS, bE);
    cudaStreamWaitEvent(0, evPad, 0);
    biaff_left<<<dim3(96, 9), 160>>>();
    biaff_right<<<dim3(9, 48), 128>>>();
    cudaEventRecord(evS, 0);

    bool scoreInOut = (out_size >= SCORE_ELEMS);
    bool didT = false;
    if (scoreInOut) {
        // s1: transpose overlaps decode (decode uses only 48 of 148 SMs)
        cudaStreamWaitEvent(s1, evS, 0);
        transpose_kernel<<<1536, 256, 0, s1>>>(out);
        cudaEventRecord(evT, s1);
        didT = true;
    }

    float* resPtr = nullptr;
    if (out_size >= SCORE_ELEMS + RESULT_ELEMS) resPtr = out + SCORE_ELEMS;
    else if (!scoreInOut && out_size >= RESULT_ELEMS) resPtr = out;

    if (resPtr) {
        decode_kernel<<<48, 1024, DEC_SMEM>>>(tagseq, resPtr);
    }

    // join s1 back into the capture stream
    if (didT) cudaStreamWaitEvent(0, evT, 0);
}